// round 16
// baseline (speedup 1.0000x reference)
#include <cuda_runtime.h>
#include <cuda_bf16.h>
#include <cstdint>

#define B 8192
#define D 128
#define KD 128
#define AST 136           // smem row stride in bf16 (272B, conflict-free ldmatrix)
#define NCTA 148
#define NJOBS 2080        // symmetric unordered strip pairs
#define TPB 512
#define FEPS 1e-5f

// ---------------- device scratch ----------------
__device__ float    g_sq[B];
__device__ float2   g_sl[B];          // (sq_j, label bits)
__device__ uint2    g_hi[B * 32];     // bf16 rows ([B][D] bf16 = 2MB)
__device__ unsigned g_m1u[B];         // monotone-encoded same-class min
__device__ unsigned g_mnu[B];         // monotone-encoded diff-class min
__device__ float    g_bsum[64];
__device__ unsigned g_cnt;

// smem byte offsets
#define SM_A   0
#define SM_B0  34816
#define SM_B1  69632
#define SM_ST  104448                  // staging float[4][2][128] = 4096B
#define SMEM_TOTAL 110592

__device__ __forceinline__ uint32_t s2u(const void* p) {
    uint32_t a;
    asm("{ .reg .u64 t; cvta.to.shared.u64 t, %1; cvt.u32.u64 %0, t; }" : "=r"(a) : "l"(p));
    return a;
}
__device__ __forceinline__ void cpa16(uint32_t dst, const void* src) {
    asm volatile("cp.async.cg.shared.global [%0], [%1], 16;" :: "r"(dst), "l"(src));
}
#define CP_COMMIT() asm volatile("cp.async.commit_group;" ::: "memory")
#define CP_WAIT0()  asm volatile("cp.async.wait_group 0;" ::: "memory")

__device__ __forceinline__ void ldsm4(uint32_t& r0, uint32_t& r1, uint32_t& r2,
                                      uint32_t& r3, uint32_t a) {
    asm volatile("ldmatrix.sync.aligned.m8n8.x4.shared.b16 {%0,%1,%2,%3}, [%4];"
                 : "=r"(r0), "=r"(r1), "=r"(r2), "=r"(r3) : "r"(a));
}
__device__ __forceinline__ void mma16816(float* c, const uint32_t* a, const uint32_t* b) {
    asm volatile(
        "mma.sync.aligned.m16n8k16.row.col.f32.bf16.bf16.f32 "
        "{%0,%1,%2,%3}, {%4,%5,%6,%7}, {%8,%9}, {%0,%1,%2,%3};"
        : "+f"(c[0]), "+f"(c[1]), "+f"(c[2]), "+f"(c[3])
        : "r"(a[0]), "r"(a[1]), "r"(a[2]), "r"(a[3]), "r"(b[0]), "r"(b[1]));
}

// monotone float<->uint encoding (min-preserving)
__device__ __forceinline__ unsigned encf(float f) {
    unsigned u = __float_as_uint(f);
    return (u >> 31) ? ~u : (u | 0x80000000u);
}
__device__ __forceinline__ float decf(unsigned u) {
    return (u & 0x80000000u) ? __uint_as_float(u ^ 0x80000000u)
                             : __uint_as_float(~u);
}

// job id -> (it, off): its 0..31 carry 33 jobs (off 0..32), its 32..63 carry 32
__device__ __forceinline__ void job2 (int g, int& it, int& off) {
    if (g < 1056) { it = g / 33; off = g - it * 33; }
    else          { int r = g - 1056; it = 32 + (r >> 5); off = r & 31; }
}
__device__ __forceinline__ int seg_end(int it) {
    return (it < 32) ? (it * 33 + 33) : (1056 + (it - 31) * 32);
}

// ---------------- prepass: bf16 convert + row norms + tracker init ----------------
__global__ void prep_kernel(const float* __restrict__ F, const int* __restrict__ lab) {
    int gtid = blockIdx.x * blockDim.x + threadIdx.x;
    int row  = gtid >> 5, lane = gtid & 31;
    float4 v = reinterpret_cast<const float4*>(F)[row * 32 + lane];
    unsigned short h[4];
    h[0] = __bfloat16_as_ushort(__float2bfloat16(v.x));
    h[1] = __bfloat16_as_ushort(__float2bfloat16(v.y));
    h[2] = __bfloat16_as_ushort(__float2bfloat16(v.z));
    h[3] = __bfloat16_as_ushort(__float2bfloat16(v.w));
    g_hi[row * 32 + lane] = make_uint2((uint32_t)h[0] | ((uint32_t)h[1] << 16),
                                       (uint32_t)h[2] | ((uint32_t)h[3] << 16));
    float s = v.x * v.x + v.y * v.y + v.z * v.z + v.w * v.w;
    #pragma unroll
    for (int d = 16; d > 0; d >>= 1) s += __shfl_xor_sync(0xffffffffu, s, d);
    if (lane == 0) {
        g_sq[row] = s;
        g_sl[row] = make_float2(s, __int_as_float(lab[row]));
    }
    if (gtid < B) {
        g_m1u[gtid] = 0xFF800000u;     // encoded +inf
        g_mnu[gtid] = 0xFF800000u;
    }
}

// copy a 128x128 bf16 tile (gmem row r0) into smem (AST-padded rows)
__device__ __forceinline__ void issue_tile(uint32_t smb, int dst_off, int r0, int tid) {
    const char* base = reinterpret_cast<const char*>(g_hi);
    #pragma unroll
    for (int p = 0; p < 4; p++) {
        int c   = p * TPB + tid;
        int row = c >> 4, off = c & 15;
        cpa16(smb + dst_off + row * (AST * 2) + off * 16,
              base + (r0 + row) * 256 + off * 16);
    }
}

// ---------------- symmetric HMMA + row/col hard-mining (148 persistent CTAs) ----------------
__global__ __launch_bounds__(TPB)
void hmma_kernel(const int* __restrict__ lab) {
    extern __shared__ char smem[];
    const uint32_t smb = s2u(smem);
    const int tid  = threadIdx.x;
    const int wid  = tid >> 5, lane = tid & 31;
    const int wm   = wid >> 2, wn = wid & 3;     // warp grid 4x4, warp tile 32x32
    const int q    = lane >> 2, tq = lane & 3;
    const float FINF = __int_as_float(0x7f800000);

    const int cb = blockIdx.x;
    int       g  = (NJOBS * cb) / NCTA;
    const int g1 = (NJOBS * (cb + 1)) / NCTA;

    // ldmatrix per-thread addresses
    const int lrow = lane & 7, grp = lane >> 3;
    int arow[2];
    #pragma unroll
    for (int mt = 0; mt < 2; mt++)
        arow[mt] = (wm * 32 + mt * 16 + lrow + (grp & 1) * 8) * AST;
    const int acol = (grp >> 1) * 8;
    int bb[2];
    #pragma unroll
    for (int ntp = 0; ntp < 2; ntp++)
        bb[ntp] = (wn * 32 + ntp * 16 + ((grp >> 1) & 1) * 8 + lrow) * AST
                + (grp & 1) * 8;

    float* st = reinterpret_cast<float*>(smem + SM_ST);
    int bufc = 0;
    bool first = true;

    while (g < g1) {
        int it, off0;
        job2(g, it, off0);
        const int sEnd = min(g1, seg_end(it));
        const int i0   = it * 128;

        issue_tile(smb, SM_A, i0, tid);
        if (first) {
            issue_tile(smb, bufc ? SM_B1 : SM_B0, (((it + off0) & 63)) * 128, tid);
            first = false;
        }
        CP_COMMIT();

        int li[2][2];
        float sqa[2][2];
        #pragma unroll
        for (int mt = 0; mt < 2; mt++)
            #pragma unroll
            for (int h = 0; h < 2; h++) {
                int i = i0 + wm * 32 + mt * 16 + q + 8 * h;
                li[mt][h]  = lab[i];
                sqa[mt][h] = g_sq[i];
            }

        float m1[4], mn[4];
        #pragma unroll
        for (int r = 0; r < 4; r++) { m1[r] = FINF; mn[r] = FINF; }

        CP_WAIT0();
        __syncthreads();

        for (; g < sEnd; g++) {
            int itc, off;
            job2(g, itc, off);
            const int jt   = (it + off) & 63;
            const int j0   = jt * 128;
            const int bufo = bufc ? SM_B1 : SM_B0;
            if (g + 1 < g1) {
                int itn, offn;
                job2(g + 1, itn, offn);
                issue_tile(smb, bufc ? SM_B0 : SM_B1, (((itn + offn) & 63)) * 128, tid);
                CP_COMMIT();
            }

            float acc[2][4][4];
            #pragma unroll
            for (int mt = 0; mt < 2; mt++)
                #pragma unroll
                for (int nt = 0; nt < 4; nt++)
                    #pragma unroll
                    for (int e = 0; e < 4; e++) acc[mt][nt][e] = 0.f;

            #pragma unroll
            for (int ks = 0; ks < KD / 16; ks++) {
                const int k0 = ks * 16;
                uint32_t a[2][4], b[4][2];
                #pragma unroll
                for (int mt = 0; mt < 2; mt++)
                    ldsm4(a[mt][0], a[mt][1], a[mt][2], a[mt][3],
                          smb + SM_A + (arow[mt] + k0 + acol) * 2);
                ldsm4(b[0][0], b[0][1], b[1][0], b[1][1],
                      smb + bufo + (bb[0] + k0) * 2);
                ldsm4(b[2][0], b[2][1], b[3][0], b[3][1],
                      smb + bufo + (bb[1] + k0) * 2);
                #pragma unroll
                for (int mt = 0; mt < 2; mt++)
                    #pragma unroll
                    for (int nt = 0; nt < 4; nt++)
                        mma16816(acc[mt][nt], a[mt], b[nt]);
            }

            if (off == 0) {
                // diagonal: full tile covers both orderings -> row-only + self-exclusion
                #pragma unroll
                for (int nt = 0; nt < 4; nt++) {
                    const int jl0 = wn * 32 + nt * 8 + 2 * tq;
                    float2 sl0 = g_sl[j0 + jl0], sl1 = g_sl[j0 + jl0 + 1];
                    const int lj0 = __float_as_int(sl0.y), lj1 = __float_as_int(sl1.y);
                    #pragma unroll
                    for (int mt = 0; mt < 2; mt++)
                        #pragma unroll
                        for (int h = 0; h < 2; h++) {
                            const int r   = mt * 2 + h;
                            const int lir = li[mt][h];
                            const int il  = wm * 32 + mt * 16 + q + 8 * h;
                            const float t0 = fmaf(-2.f, acc[mt][nt][2 * h],     sl0.x);
                            const float t1 = fmaf(-2.f, acc[mt][nt][2 * h + 1], sl1.x);
                            const bool s0 = (lir == lj0) & (jl0 != il);
                            const bool n0 = (lir != lj0);
                            const bool s1 = (lir == lj1) & (jl0 + 1 != il);
                            const bool n1 = (lir != lj1);
                            m1[r] = fminf(m1[r], s0 ? t0 : FINF);
                            mn[r] = fminf(mn[r], n0 ? t0 : FINF);
                            m1[r] = fminf(m1[r], s1 ? t1 : FINF);
                            mn[r] = fminf(mn[r], n1 ? t1 : FINF);
                        }
                }
            } else {
                // off-diagonal: row + col trackers (pair counted once)
                float c1[8], cn[8];
                #pragma unroll
                for (int ci = 0; ci < 8; ci++) { c1[ci] = FINF; cn[ci] = FINF; }
                #pragma unroll
                for (int nt = 0; nt < 4; nt++) {
                    const int jl0 = wn * 32 + nt * 8 + 2 * tq;
                    float2 sl0 = g_sl[j0 + jl0], sl1 = g_sl[j0 + jl0 + 1];
                    const int lj0 = __float_as_int(sl0.y), lj1 = __float_as_int(sl1.y);
                    #pragma unroll
                    for (int mt = 0; mt < 2; mt++)
                        #pragma unroll
                        for (int h = 0; h < 2; h++) {
                            const int r   = mt * 2 + h;
                            const int lir = li[mt][h];
                            const float dot0 = acc[mt][nt][2 * h];
                            const float dot1 = acc[mt][nt][2 * h + 1];
                            const float t0 = fmaf(-2.f, dot0, sl0.x);
                            const float t1 = fmaf(-2.f, dot1, sl1.x);
                            const float u0 = fmaf(-2.f, dot0, sqa[mt][h]);
                            const float u1 = fmaf(-2.f, dot1, sqa[mt][h]);
                            const bool s0 = (lir == lj0), s1 = (lir == lj1);
                            m1[r] = fminf(m1[r], s0 ? t0 : FINF);
                            mn[r] = fminf(mn[r], s0 ? FINF : t0);
                            m1[r] = fminf(m1[r], s1 ? t1 : FINF);
                            mn[r] = fminf(mn[r], s1 ? FINF : t1);
                            c1[nt * 2]     = fminf(c1[nt * 2],     s0 ? u0 : FINF);
                            cn[nt * 2]     = fminf(cn[nt * 2],     s0 ? FINF : u0);
                            c1[nt * 2 + 1] = fminf(c1[nt * 2 + 1], s1 ? u1 : FINF);
                            cn[nt * 2 + 1] = fminf(cn[nt * 2 + 1], s1 ? FINF : u1);
                        }
                }
                // col reduce across q (lane bits 2..4), stage across wm, atomic flush
                #pragma unroll
                for (int d = 4; d < 32; d <<= 1) {
                    #pragma unroll
                    for (int ci = 0; ci < 8; ci++) {
                        c1[ci] = fminf(c1[ci], __shfl_xor_sync(0xffffffffu, c1[ci], d));
                        cn[ci] = fminf(cn[ci], __shfl_xor_sync(0xffffffffu, cn[ci], d));
                    }
                }
                if (q == 0) {
                    #pragma unroll
                    for (int nt = 0; nt < 4; nt++)
                        #pragma unroll
                        for (int p = 0; p < 2; p++) {
                            int col = wn * 32 + nt * 8 + 2 * tq + p;
                            st[wm * 256 + 0 * 128 + col] = c1[nt * 2 + p];
                            st[wm * 256 + 1 * 128 + col] = cn[nt * 2 + p];
                        }
                }
                __syncthreads();
                if (tid < 128) {
                    float a1 = FINF, an = FINF;
                    #pragma unroll
                    for (int w = 0; w < 4; w++) {
                        a1 = fminf(a1, st[w * 256 + tid]);
                        an = fminf(an, st[w * 256 + 128 + tid]);
                    }
                    atomicMin(&g_m1u[j0 + tid], encf(a1));
                    atomicMin(&g_mnu[j0 + tid], encf(an));
                }
            }

            if (g + 1 < g1) CP_WAIT0();
            __syncthreads();
            bufc ^= 1;
        }

        // ---- segment row flush ----
        #pragma unroll
        for (int d = 1; d < 4; d <<= 1) {
            #pragma unroll
            for (int r = 0; r < 4; r++) {
                m1[r] = fminf(m1[r], __shfl_xor_sync(0xffffffffu, m1[r], d));
                mn[r] = fminf(mn[r], __shfl_xor_sync(0xffffffffu, mn[r], d));
            }
        }
        if (tq == 0) {
            #pragma unroll
            for (int mt = 0; mt < 2; mt++)
                #pragma unroll
                for (int h = 0; h < 2; h++) {
                    int r = wm * 32 + mt * 16 + q + 8 * h;
                    st[wn * 256 + 0 * 128 + r] = m1[mt * 2 + h];
                    st[wn * 256 + 1 * 128 + r] = mn[mt * 2 + h];
                }
        }
        __syncthreads();
        if (tid < 128) {
            float a1 = FINF, an = FINF;
            #pragma unroll
            for (int w = 0; w < 4; w++) {
                a1 = fminf(a1, st[w * 256 + tid]);
                an = fminf(an, st[w * 256 + 128 + tid]);
            }
            atomicMin(&g_m1u[i0 + tid], encf(a1));
            atomicMin(&g_mnu[i0 + tid], encf(an));
        }
        __syncthreads();
    }
}

// ---------------- fused merge: hinge + mean (last-block-done) ----------------
__global__ void merge_kernel(float* __restrict__ out) {
    const int tid = threadIdx.x;
    const int row = blockIdx.x * 128 + tid;
    __shared__ float red[128];
    __shared__ int   slast;
    float a1 = decf(g_m1u[row]);
    float an = decf(g_mnu[row]);
    float sqi = g_sq[row];
    float pos = sqrtf(fmaxf(sqi + a1 + FEPS, 0.f));
    float neg = sqrtf(fmaxf(sqi + an + FEPS, 0.f));
    red[tid] = fmaxf(1.0f + pos - neg, 0.f);
    __syncthreads();
    for (int s = 64; s > 0; s >>= 1) {
        if (tid < s) red[tid] += red[tid + s];
        __syncthreads();
    }
    if (tid == 0) {
        g_bsum[blockIdx.x] = red[0];
        __threadfence();
        unsigned t = atomicAdd(&g_cnt, 1u);
        slast = (t == 63u);
    }
    __syncthreads();
    if (slast) {
        red[tid] = (tid < 64) ? g_bsum[tid] : 0.f;
        __syncthreads();
        for (int s = 64; s > 0; s >>= 1) {
            if (tid < s) red[tid] += red[tid + s];
            __syncthreads();
        }
        if (tid == 0) {
            out[0] = red[0] * (1.0f / (float)B);
            g_cnt = 0u;          // reset for next graph replay
        }
    }
}

extern "C" void kernel_launch(void* const* d_in, const int* in_sizes, int n_in,
                              void* d_out, int out_size) {
    (void)in_sizes; (void)n_in; (void)out_size;
    const float* F   = (const float*)d_in[0];
    const int*   lab = (const int*)d_in[1];
    float*       out = (float*)d_out;

    cudaFuncSetAttribute(hmma_kernel,
                         cudaFuncAttributeMaxDynamicSharedMemorySize, SMEM_TOTAL);

    prep_kernel<<<B * 32 / 256, 256>>>(F, lab);
    hmma_kernel<<<NCTA, TPB, SMEM_TOTAL>>>(lab);
    merge_kernel<<<64, 128>>>(out);
}

// round 17
// speedup vs baseline: 1.4155x; 1.4155x over previous
#include <cuda_runtime.h>
#include <cuda_bf16.h>
#include <cstdint>

#define B 8192
#define D 128
#define KD 128
#define AST 136           // smem row stride in bf16 (272B, conflict-free ldmatrix)
#define NCTA 148          // one CTA per SM, balanced job ranges
#define NJOBS 4096        // 64 it-strips x 64 jt
#define TPB 512
#define FEPS 1e-5f

// ---------------- device scratch ----------------
__device__ float    g_sq[B];
__device__ float2   g_sl[B];          // (sq_j, label bits)
__device__ uint2    g_hi[B * 32];     // bf16 rows ([B][D] bf16 = 2MB)
__device__ unsigned g_m1u[B];         // monotone-encoded same-class min
__device__ unsigned g_mnu[B];         // monotone-encoded diff-class min
__device__ float    g_bsum[64];
__device__ unsigned g_cnt;

// smem byte offsets
#define SM_A   0
#define SM_B0  34816
#define SM_B1  69632
#define SM_ST  104448                  // staging float[4][2][128] = 4096B
#define SMEM_TOTAL 110592

__device__ __forceinline__ uint32_t s2u(const void* p) {
    uint32_t a;
    asm("{ .reg .u64 t; cvta.to.shared.u64 t, %1; cvt.u32.u64 %0, t; }" : "=r"(a) : "l"(p));
    return a;
}
__device__ __forceinline__ void cpa16(uint32_t dst, const void* src) {
    asm volatile("cp.async.cg.shared.global [%0], [%1], 16;" :: "r"(dst), "l"(src));
}
#define CP_COMMIT() asm volatile("cp.async.commit_group;" ::: "memory")
#define CP_WAIT0()  asm volatile("cp.async.wait_group 0;" ::: "memory")

__device__ __forceinline__ void ldsm4(uint32_t& r0, uint32_t& r1, uint32_t& r2,
                                      uint32_t& r3, uint32_t a) {
    asm volatile("ldmatrix.sync.aligned.m8n8.x4.shared.b16 {%0,%1,%2,%3}, [%4];"
                 : "=r"(r0), "=r"(r1), "=r"(r2), "=r"(r3) : "r"(a));
}
__device__ __forceinline__ void mma16816(float* c, const uint32_t* a, const uint32_t* b) {
    asm volatile(
        "mma.sync.aligned.m16n8k16.row.col.f32.bf16.bf16.f32 "
        "{%0,%1,%2,%3}, {%4,%5,%6,%7}, {%8,%9}, {%0,%1,%2,%3};"
        : "+f"(c[0]), "+f"(c[1]), "+f"(c[2]), "+f"(c[3])
        : "r"(a[0]), "r"(a[1]), "r"(a[2]), "r"(a[3]), "r"(b[0]), "r"(b[1]));
}

// monotone float<->uint encoding (min-preserving)
__device__ __forceinline__ unsigned encf(float f) {
    unsigned u = __float_as_uint(f);
    return (u >> 31) ? ~u : (u | 0x80000000u);
}
__device__ __forceinline__ float decf(unsigned u) {
    return (u & 0x80000000u) ? __uint_as_float(u ^ 0x80000000u)
                             : __uint_as_float(~u);
}

// ---------------- prepass: bf16 convert + row norms + tracker init ----------------
__global__ void prep_kernel(const float* __restrict__ F, const int* __restrict__ lab) {
    int gtid = blockIdx.x * blockDim.x + threadIdx.x;
    int row  = gtid >> 5, lane = gtid & 31;
    float4 v = reinterpret_cast<const float4*>(F)[row * 32 + lane];
    unsigned short h[4];
    h[0] = __bfloat16_as_ushort(__float2bfloat16(v.x));
    h[1] = __bfloat16_as_ushort(__float2bfloat16(v.y));
    h[2] = __bfloat16_as_ushort(__float2bfloat16(v.z));
    h[3] = __bfloat16_as_ushort(__float2bfloat16(v.w));
    g_hi[row * 32 + lane] = make_uint2((uint32_t)h[0] | ((uint32_t)h[1] << 16),
                                       (uint32_t)h[2] | ((uint32_t)h[3] << 16));
    float s = v.x * v.x + v.y * v.y + v.z * v.z + v.w * v.w;
    #pragma unroll
    for (int d = 16; d > 0; d >>= 1) s += __shfl_xor_sync(0xffffffffu, s, d);
    if (lane == 0) {
        g_sq[row] = s;
        g_sl[row] = make_float2(s, __int_as_float(lab[row]));
    }
    if (gtid < B) {                       // encoded +inf
        g_m1u[gtid] = 0xFF800000u;
        g_mnu[gtid] = 0xFF800000u;
    }
}

// copy a 128x128 bf16 tile (gmem row r0) into smem (AST-padded rows)
__device__ __forceinline__ void issue_tile(uint32_t smb, int dst_off, int r0, int tid) {
    const char* base = reinterpret_cast<const char*>(g_hi);
    #pragma unroll
    for (int p = 0; p < 4; p++) {
        int c   = p * TPB + tid;
        int row = c >> 4, off = c & 15;
        cpa16(smb + dst_off + row * (AST * 2) + off * 16,
              base + (r0 + row) * 256 + off * 16);
    }
}

// ---------------- main HMMA + hard-mining kernel (148 balanced CTAs) ----------------
__global__ __launch_bounds__(TPB)
void hmma_kernel(const int* __restrict__ lab) {
    extern __shared__ char smem[];
    const uint32_t smb = s2u(smem);
    const int tid  = threadIdx.x;
    const int wid  = tid >> 5, lane = tid & 31;
    const int wm   = wid >> 2, wn = wid & 3;     // warp grid 4x4, warp tile 32x32
    const int q    = lane >> 2, tq = lane & 3;
    const float FINF = __int_as_float(0x7f800000);

    const int c  = blockIdx.x;
    int       g  = (NJOBS * c) / NCTA;
    const int g1 = (NJOBS * (c + 1)) / NCTA;

    // ldmatrix per-thread addresses
    const int lrow = lane & 7, grp = lane >> 3;
    int arow[2];
    #pragma unroll
    for (int mt = 0; mt < 2; mt++)
        arow[mt] = (wm * 32 + mt * 16 + lrow + (grp & 1) * 8) * AST;
    const int acol = (grp >> 1) * 8;
    int bb[2];
    #pragma unroll
    for (int ntp = 0; ntp < 2; ntp++)
        bb[ntp] = (wn * 32 + ntp * 16 + ((grp >> 1) & 1) * 8 + lrow) * AST
                + (grp & 1) * 8;

    float* st = reinterpret_cast<float*>(smem + SM_ST);
    int bufc = 0;
    bool first = true;

    while (g < g1) {
        const int it     = g >> 6;
        const int segEnd = min(g1, (it + 1) << 6);
        const int i0     = it * 128;

        // segment prologue: A tile (+ first B if nothing prefetched)
        issue_tile(smb, SM_A, i0, tid);
        if (first) {
            issue_tile(smb, bufc ? SM_B1 : SM_B0, (g & 63) * 128, tid);
            first = false;
        }
        CP_COMMIT();

        int li[2][2];
        #pragma unroll
        for (int mt = 0; mt < 2; mt++) {
            li[mt][0] = lab[i0 + wm * 32 + mt * 16 + q];
            li[mt][1] = lab[i0 + wm * 32 + mt * 16 + q + 8];
        }

        float m1[4], mn[4];
        #pragma unroll
        for (int r = 0; r < 4; r++) { m1[r] = FINF; mn[r] = FINF; }

        CP_WAIT0();
        __syncthreads();

        // ---- hoist A fragments for the whole segment (loop-invariant) ----
        uint32_t af[8][2][4];
        #pragma unroll
        for (int ks = 0; ks < 8; ks++)
            #pragma unroll
            for (int mt = 0; mt < 2; mt++)
                ldsm4(af[ks][mt][0], af[ks][mt][1], af[ks][mt][2], af[ks][mt][3],
                      smb + SM_A + (arow[mt] + ks * 16 + acol) * 2);

        for (; g < segEnd; g++) {
            const int bufo = bufc ? SM_B1 : SM_B0;
            if (g + 1 < g1) {
                issue_tile(smb, bufc ? SM_B0 : SM_B1, ((g + 1) & 63) * 128, tid);
                CP_COMMIT();
            }

            float acc[2][4][4];
            #pragma unroll
            for (int mt = 0; mt < 2; mt++)
                #pragma unroll
                for (int nt = 0; nt < 4; nt++)
                    #pragma unroll
                    for (int e = 0; e < 4; e++) acc[mt][nt][e] = 0.f;

            #pragma unroll
            for (int ks = 0; ks < KD / 16; ks++) {
                const int k0 = ks * 16;
                uint32_t b[4][2];
                ldsm4(b[0][0], b[0][1], b[1][0], b[1][1],
                      smb + bufo + (bb[0] + k0) * 2);
                ldsm4(b[2][0], b[2][1], b[3][0], b[3][1],
                      smb + bufo + (bb[1] + k0) * 2);
                #pragma unroll
                for (int mt = 0; mt < 2; mt++)
                    #pragma unroll
                    for (int nt = 0; nt < 4; nt++)
                        mma16816(acc[mt][nt], af[ks][mt], b[nt]);
            }

            // ---- thin BRANCHLESS epilogue ----
            const int jt = g & 63;
            const int j0 = jt * 128;
            if (jt != it) {
                #pragma unroll
                for (int nt = 0; nt < 4; nt++) {
                    const int jl0 = wn * 32 + nt * 8 + 2 * tq;
                    float2 sl0 = g_sl[j0 + jl0], sl1 = g_sl[j0 + jl0 + 1];
                    const int lj0 = __float_as_int(sl0.y), lj1 = __float_as_int(sl1.y);
                    #pragma unroll
                    for (int mt = 0; mt < 2; mt++)
                        #pragma unroll
                        for (int h = 0; h < 2; h++) {
                            const int r   = mt * 2 + h;
                            const int lir = li[mt][h];
                            const float t0 = fmaf(-2.f, acc[mt][nt][2 * h],     sl0.x);
                            const float t1 = fmaf(-2.f, acc[mt][nt][2 * h + 1], sl1.x);
                            const bool s0 = (lir == lj0), s1 = (lir == lj1);
                            m1[r] = fminf(m1[r], s0 ? t0 : FINF);
                            mn[r] = fminf(mn[r], s0 ? FINF : t0);
                            m1[r] = fminf(m1[r], s1 ? t1 : FINF);
                            mn[r] = fminf(mn[r], s1 ? FINF : t1);
                        }
                }
            } else {
                #pragma unroll
                for (int nt = 0; nt < 4; nt++) {
                    const int jl0 = wn * 32 + nt * 8 + 2 * tq;
                    float2 sl0 = g_sl[j0 + jl0], sl1 = g_sl[j0 + jl0 + 1];
                    const int lj0 = __float_as_int(sl0.y), lj1 = __float_as_int(sl1.y);
                    #pragma unroll
                    for (int mt = 0; mt < 2; mt++)
                        #pragma unroll
                        for (int h = 0; h < 2; h++) {
                            const int r   = mt * 2 + h;
                            const int lir = li[mt][h];
                            const int il  = wm * 32 + mt * 16 + q + 8 * h;
                            const float t0 = fmaf(-2.f, acc[mt][nt][2 * h],     sl0.x);
                            const float t1 = fmaf(-2.f, acc[mt][nt][2 * h + 1], sl1.x);
                            const bool s0 = (lir == lj0) & (jl0 != il);
                            const bool n0 = (lir != lj0);
                            const bool s1 = (lir == lj1) & (jl0 + 1 != il);
                            const bool n1 = (lir != lj1);
                            m1[r] = fminf(m1[r], s0 ? t0 : FINF);
                            mn[r] = fminf(mn[r], n0 ? t0 : FINF);
                            m1[r] = fminf(m1[r], s1 ? t1 : FINF);
                            mn[r] = fminf(mn[r], n1 ? t1 : FINF);
                        }
                }
            }

            if (g + 1 < g1) CP_WAIT0();
            __syncthreads();
            bufc ^= 1;
        }

        // ---- segment flush: reduce trackers, atomicMin to global ----
        #pragma unroll
        for (int d = 1; d < 4; d <<= 1) {
            #pragma unroll
            for (int r = 0; r < 4; r++) {
                m1[r] = fminf(m1[r], __shfl_xor_sync(0xffffffffu, m1[r], d));
                mn[r] = fminf(mn[r], __shfl_xor_sync(0xffffffffu, mn[r], d));
            }
        }
        if (tq == 0) {
            #pragma unroll
            for (int mt = 0; mt < 2; mt++)
                #pragma unroll
                for (int h = 0; h < 2; h++) {
                    int r = wm * 32 + mt * 16 + q + 8 * h;
                    st[wn * 256 + 0 * 128 + r] = m1[mt * 2 + h];
                    st[wn * 256 + 1 * 128 + r] = mn[mt * 2 + h];
                }
        }
        __syncthreads();
        if (tid < 128) {
            float a1 = FINF, an = FINF;
            #pragma unroll
            for (int w = 0; w < 4; w++) {
                a1 = fminf(a1, st[w * 256 + tid]);
                an = fminf(an, st[w * 256 + 128 + tid]);
            }
            atomicMin(&g_m1u[i0 + tid], encf(a1));
            atomicMin(&g_mnu[i0 + tid], encf(an));
        }
        __syncthreads();
    }
}

// ---------------- fused merge: hinge + mean (last-block-done) ----------------
__global__ void merge_kernel(float* __restrict__ out) {
    const int tid = threadIdx.x;
    const int row = blockIdx.x * 128 + tid;
    __shared__ float red[128];
    __shared__ int   slast;
    float a1 = decf(g_m1u[row]);
    float an = decf(g_mnu[row]);
    float sqi = g_sq[row];
    float pos = sqrtf(fmaxf(sqi + a1 + FEPS, 0.f));
    float neg = sqrtf(fmaxf(sqi + an + FEPS, 0.f));
    red[tid] = fmaxf(1.0f + pos - neg, 0.f);
    __syncthreads();
    for (int s = 64; s > 0; s >>= 1) {
        if (tid < s) red[tid] += red[tid + s];
        __syncthreads();
    }
    if (tid == 0) {
        g_bsum[blockIdx.x] = red[0];
        __threadfence();
        unsigned t = atomicAdd(&g_cnt, 1u);
        slast = (t == 63u);
    }
    __syncthreads();
    if (slast) {
        red[tid] = (tid < 64) ? g_bsum[tid] : 0.f;
        __syncthreads();
        for (int s = 64; s > 0; s >>= 1) {
            if (tid < s) red[tid] += red[tid + s];
            __syncthreads();
        }
        if (tid == 0) {
            out[0] = red[0] * (1.0f / (float)B);
            g_cnt = 0u;          // reset for next graph replay
        }
    }
}

extern "C" void kernel_launch(void* const* d_in, const int* in_sizes, int n_in,
                              void* d_out, int out_size) {
    (void)in_sizes; (void)n_in; (void)out_size;
    const float* F   = (const float*)d_in[0];
    const int*   lab = (const int*)d_in[1];
    float*       out = (float*)d_out;

    cudaFuncSetAttribute(hmma_kernel,
                         cudaFuncAttributeMaxDynamicSharedMemorySize, SMEM_TOTAL);

    prep_kernel<<<B * 32 / 256, 256>>>(F, lab);
    hmma_kernel<<<NCTA, TPB, SMEM_TOTAL>>>(lab);
    merge_kernel<<<64, 128>>>(out);
}